// round 3
// baseline (speedup 1.0000x reference)
#include <cuda_runtime.h>
#include <math.h>

// Problem constants
#define BB   8192
#define II   1024
#define HH   1024
#define MSS  64
#define MM   16
#define TAUF 1.0f

#define BHsz (BB * HH)            // 8388608

// Scratch (static __device__ arrays — no allocations allowed)
__device__ float g_act[3u * BHsz];      // activated i, f, cand  (~100 MB)
__device__ float g_cnew[BHsz];          // c_new contiguous [B,H]
__device__ float g_hnew[BHsz];          // h_new contiguous [B,H]
__device__ float g_micro[BB * MSS];     // micro [B,64]

__device__ __forceinline__ float sigmoidf_(float v) {
    return 1.0f / (1.0f + expf(-v));
}

// ---------------------------------------------------------------------------
// Main GEMM: out[b,n] = act( sum_k A[b,k] * W[k,n] + bias[n] )
// A is the virtual concat [x | h | (c or c_new)] with per-1024 segment select.
// gate: 0 = i (sigmoid -> g_act[0]), 1 = f (sigmoid -> g_act[1]),
//       2 = cand (tanh -> g_act[2], K=2048),
//       3 = o (sigmoid; h_new = o*tanh(c_new) -> g_hnew and out[:, :1024])
// Tiling: 128x128 block, BK=32, 256 threads, 8x8 per thread.
// ---------------------------------------------------------------------------
#define BM 128
#define BN 128
#define BK 32

__global__ __launch_bounds__(256) void gemm_act(
    const float* __restrict__ Ax,
    const float* __restrict__ Ah,
    const float* __restrict__ Ac,      // c for gates 0/1; ignored for 2; g_cnew for 3
    const float* __restrict__ W,       // [K, 1024] row-major
    const float* __restrict__ bias,    // [1024]
    int K, int gate,
    float* __restrict__ outp)          // only used by gate==3
{
    __shared__ float sA[BK][BM + 4];   // transposed A tile, padded
    __shared__ float sB[BK][BN];

    const int bm = blockIdx.y * BM;
    const int bn = blockIdx.x * BN;
    const int tid = threadIdx.x;
    const int tx = tid & 15;           // 0..15
    const int ty = tid >> 4;           // 0..15

    const float* A2p = (gate == 3) ? g_cnew : Ac;

    float acc[8][8];
#pragma unroll
    for (int i = 0; i < 8; i++)
#pragma unroll
        for (int j = 0; j < 8; j++) acc[i][j] = 0.0f;

    for (int k0 = 0; k0 < K; k0 += BK) {
        // Select concat segment (tiles never straddle 1024 boundaries)
        const float* Aseg;
        int koff;
        if (k0 < 1024)      { Aseg = Ax;  koff = k0; }
        else if (k0 < 2048) { Aseg = Ah;  koff = k0 - 1024; }
        else                { Aseg = A2p; koff = k0 - 2048; }

        // Load A tile: 128 rows x 32 k  (1024 float4, 4 per thread), transpose
#pragma unroll
        for (int i = 0; i < 4; i++) {
            int idx = tid + i * 256;
            int r  = idx >> 3;
            int c4 = (idx & 7) * 4;
            float4 v = *(const float4*)&Aseg[(size_t)(bm + r) * 1024 + koff + c4];
            sA[c4 + 0][r] = v.x;
            sA[c4 + 1][r] = v.y;
            sA[c4 + 2][r] = v.z;
            sA[c4 + 3][r] = v.w;
        }
        // Load B tile: 32 k x 128 n
#pragma unroll
        for (int i = 0; i < 4; i++) {
            int idx = tid + i * 256;
            int r  = idx >> 5;
            int c4 = (idx & 31) * 4;
            *(float4*)&sB[r][c4] = *(const float4*)&W[(size_t)(k0 + r) * 1024 + bn + c4];
        }
        __syncthreads();

#pragma unroll
        for (int kk = 0; kk < BK; kk++) {
            float4 a0 = *(const float4*)&sA[kk][ty * 8];
            float4 a1 = *(const float4*)&sA[kk][ty * 8 + 4];
            float4 b0 = *(const float4*)&sB[kk][tx * 8];
            float4 b1 = *(const float4*)&sB[kk][tx * 8 + 4];
            float a[8] = {a0.x, a0.y, a0.z, a0.w, a1.x, a1.y, a1.z, a1.w};
            float b[8] = {b0.x, b0.y, b0.z, b0.w, b1.x, b1.y, b1.z, b1.w};
#pragma unroll
            for (int i = 0; i < 8; i++)
#pragma unroll
                for (int j = 0; j < 8; j++)
                    acc[i][j] = fmaf(a[i], b[j], acc[i][j]);
        }
        __syncthreads();
    }

    // Epilogue
    const int colbase = bn + tx * 8;
    float4 bb0 = *(const float4*)&bias[colbase];
    float4 bb1 = *(const float4*)&bias[colbase + 4];
    float bv[8] = {bb0.x, bb0.y, bb0.z, bb0.w, bb1.x, bb1.y, bb1.z, bb1.w};

#pragma unroll
    for (int i = 0; i < 8; i++) {
        const int row = bm + ty * 8 + i;
        float r[8];
#pragma unroll
        for (int j = 0; j < 8; j++) r[j] = acc[i][j] + bv[j];

        if (gate == 2) {
#pragma unroll
            for (int j = 0; j < 8; j++) r[j] = tanhf(r[j]);
        } else {
#pragma unroll
            for (int j = 0; j < 8; j++) r[j] = sigmoidf_(r[j]);
        }

        if (gate < 3) {
            float* dst = g_act + (size_t)gate * BHsz + (size_t)row * 1024 + colbase;
            *(float4*)&dst[0] = make_float4(r[0], r[1], r[2], r[3]);
            *(float4*)&dst[4] = make_float4(r[4], r[5], r[6], r[7]);
        } else {
            const float* cn = g_cnew + (size_t)row * 1024 + colbase;
            float4 c0 = *(const float4*)&cn[0];
            float4 c1 = *(const float4*)&cn[4];
            float hn[8];
            hn[0] = r[0] * tanhf(c0.x); hn[1] = r[1] * tanhf(c0.y);
            hn[2] = r[2] * tanhf(c0.z); hn[3] = r[3] * tanhf(c0.w);
            hn[4] = r[4] * tanhf(c1.x); hn[5] = r[5] * tanhf(c1.y);
            hn[6] = r[6] * tanhf(c1.z); hn[7] = r[7] * tanhf(c1.w);
            float* dh = g_hnew + (size_t)row * 1024 + colbase;
            *(float4*)&dh[0] = make_float4(hn[0], hn[1], hn[2], hn[3]);
            *(float4*)&dh[4] = make_float4(hn[4], hn[5], hn[6], hn[7]);
            // out row stride is 2050 floats (8200 B): only 8-byte aligned.
            float* doo = outp + (size_t)row * 2050 + colbase;
            *(float2*)&doo[0] = make_float2(hn[0], hn[1]);
            *(float2*)&doo[2] = make_float2(hn[2], hn[3]);
            *(float2*)&doo[4] = make_float2(hn[4], hn[5]);
            *(float2*)&doo[6] = make_float2(hn[6], hn[7]);
        }
    }
}

// ---------------------------------------------------------------------------
// c_new = f*c + i*cand ; write to g_cnew and out[:, 1024:2048]
// ---------------------------------------------------------------------------
__global__ __launch_bounds__(256) void cnew_kernel(
    const float* __restrict__ c, float* __restrict__ outp)
{
    size_t i4 = (size_t)blockIdx.x * 256 + threadIdx.x;   // over BH/4
    size_t idx = i4 * 4;
    float4 gi = *(const float4*)&g_act[idx];
    float4 gf = *(const float4*)&g_act[(size_t)BHsz + idx];
    float4 gp = *(const float4*)&g_act[2ull * BHsz + idx];
    float4 cv = *(const float4*)&c[idx];
    float4 cn;
    cn.x = gf.x * cv.x + gi.x * gp.x;
    cn.y = gf.y * cv.y + gi.y * gp.y;
    cn.z = gf.z * cv.z + gi.z * gp.z;
    cn.w = gf.w * cv.w + gi.w * gp.w;
    *(float4*)&g_cnew[idx] = cn;
    size_t row = idx >> 10;
    size_t col = idx & 1023;
    // out row stride 2050 floats: 8-byte aligned only -> float2 stores
    float* doo = &outp[row * 2050 + 1024 + col];
    *(float2*)&doo[0] = make_float2(cn.x, cn.y);
    *(float2*)&doo[2] = make_float2(cn.z, cn.w);
}

// ---------------------------------------------------------------------------
// micro = h_new @ W_m + b_m   ([B,1024] @ [1024,64])
// Block: 64 rows x 64 cols, 256 threads, 4x4 per thread.
// ---------------------------------------------------------------------------
__global__ __launch_bounds__(256) void micro_gemm(
    const float* __restrict__ Wm, const float* __restrict__ bm)
{
    __shared__ float sH[64][33];
    __shared__ float sW[32][64];
    const int bm0 = blockIdx.x * 64;
    const int tid = threadIdx.x;
    const int tx = tid & 15, ty = tid >> 4;

    float acc[4][4];
#pragma unroll
    for (int i = 0; i < 4; i++)
#pragma unroll
        for (int j = 0; j < 4; j++) acc[i][j] = 0.0f;

    for (int k0 = 0; k0 < 1024; k0 += 32) {
#pragma unroll
        for (int i = 0; i < 2; i++) {
            int idx = tid + i * 256;
            int r = idx >> 3, c4 = (idx & 7) * 4;
            float4 v = *(const float4*)&g_hnew[(size_t)(bm0 + r) * 1024 + k0 + c4];
            sH[r][c4 + 0] = v.x; sH[r][c4 + 1] = v.y;
            sH[r][c4 + 2] = v.z; sH[r][c4 + 3] = v.w;
        }
#pragma unroll
        for (int i = 0; i < 2; i++) {
            int idx = tid + i * 256;
            int r = idx >> 4, c4 = (idx & 15) * 4;
            *(float4*)&sW[r][c4] = *(const float4*)&Wm[(size_t)(k0 + r) * 64 + c4];
        }
        __syncthreads();
#pragma unroll
        for (int kk = 0; kk < 32; kk++) {
            float a[4];
#pragma unroll
            for (int i = 0; i < 4; i++) a[i] = sH[ty * 4 + i][kk];
            float4 b4 = *(const float4*)&sW[kk][tx * 4];
            float b[4] = {b4.x, b4.y, b4.z, b4.w};
#pragma unroll
            for (int i = 0; i < 4; i++)
#pragma unroll
                for (int j = 0; j < 4; j++)
                    acc[i][j] = fmaf(a[i], b[j], acc[i][j]);
        }
        __syncthreads();
    }
    float4 bb = *(const float4*)&bm[tx * 4];
    float bv[4] = {bb.x, bb.y, bb.z, bb.w};
#pragma unroll
    for (int i = 0; i < 4; i++) {
        int row = bm0 + ty * 4 + i;
        float4 v = make_float4(acc[i][0] + bv[0], acc[i][1] + bv[1],
                               acc[i][2] + bv[2], acc[i][3] + bv[3]);
        *(float4*)&g_micro[(size_t)row * 64 + tx * 4] = v;
    }
}

// ---------------------------------------------------------------------------
// Finalize: logits -> gumbel softmax -> sampled -> alpha/beta. 1 block / row.
// ---------------------------------------------------------------------------
__device__ __forceinline__ float warpred(float v) {
#pragma unroll
    for (int o = 16; o > 0; o >>= 1) v += __shfl_down_sync(0xffffffffu, v, o);
    return v;
}

__global__ __launch_bounds__(256) void finalize_kernel(
    const float* __restrict__ x,
    const float* __restrict__ mem,     // [B,16,64]
    const float* __restrict__ u_gs,    // [B,16]
    const float* __restrict__ u_a, const float* __restrict__ u_b,
    const float* __restrict__ w_a_h, const float* __restrict__ w_a_x,
    const float* __restrict__ w_a_r,
    const float* __restrict__ w_b_h, const float* __restrict__ w_b_x,
    const float* __restrict__ w_b_r,
    float* __restrict__ outp)
{
    __shared__ float s_micro[64];
    __shared__ float s_part[256];
    __shared__ float s_attn[16];
    __shared__ float s_red[20];

    const int b = blockIdx.x;
    const int t = threadIdx.x;
    const int lane = t & 31, wid = t >> 5;

    const float* hrow = g_hnew + (size_t)b * 1024;
    const float* xrow = x + (size_t)b * 1024;
    const float* mrow = mem + (size_t)b * 1024;   // 16*64

    // dots over 1024 (h·w?_h + x·w?_x), 4 elems/thread
    {
        float4 h4 = *(const float4*)&hrow[t * 4];
        float4 x4 = *(const float4*)&xrow[t * 4];
        float4 ah = *(const float4*)&w_a_h[t * 4];
        float4 ax = *(const float4*)&w_a_x[t * 4];
        float4 bh = *(const float4*)&w_b_h[t * 4];
        float4 bx = *(const float4*)&w_b_x[t * 4];
        float pa = h4.x*ah.x + h4.y*ah.y + h4.z*ah.z + h4.w*ah.w
                 + x4.x*ax.x + x4.y*ax.y + x4.z*ax.z + x4.w*ax.w;
        float pb = h4.x*bh.x + h4.y*bh.y + h4.z*bh.z + h4.w*bh.w
                 + x4.x*bx.x + x4.y*bx.y + x4.z*bx.z + x4.w*bx.w;
        pa = warpred(pa); pb = warpred(pb);
        if (lane == 0) { s_red[wid] = pa; s_red[8 + wid] = pb; }
    }
    if (t < 16)
        *(float4*)&s_micro[t * 4] = *(const float4*)&g_micro[(size_t)b * 64 + t * 4];
    __syncthreads();

    // logits partials: m = t>>4 (16 m), q = t&15 (4 j each)
    {
        int m = t >> 4, q = t & 15;
        float4 m4 = *(const float4*)&mrow[m * 64 + q * 4];
        float4 u4 = *(const float4*)&s_micro[q * 4];
        s_part[t] = m4.x*u4.x + m4.y*u4.y + m4.z*u4.z + m4.w*u4.w;
    }
    __syncthreads();

    if (t < 16) {
        float lg = 0.0f;
#pragma unroll
        for (int q = 0; q < 16; q++) lg += s_part[t * 16 + q];
        float u = u_gs[(size_t)b * 16 + t];
        lg += -logf(-logf(u));
        lg /= TAUF;
        float mx = lg;
#pragma unroll
        for (int o = 8; o > 0; o >>= 1)
            mx = fmaxf(mx, __shfl_xor_sync(0xffffu, mx, o));
        float e = expf(lg - mx);
        float s = e;
#pragma unroll
        for (int o = 8; o > 0; o >>= 1)
            s += __shfl_xor_sync(0xffffu, s, o);
        s_attn[t] = e / s;
    }
    __syncthreads();

    if (t < 64) {
        float sv = 0.0f;
#pragma unroll
        for (int m = 0; m < 16; m++) sv += mrow[m * 64 + t] * s_attn[m];
        sv += 1.0f;
        float ra = sv * w_a_r[t];
        float rb = sv * w_b_r[t];
        ra = warpred(ra); rb = warpred(rb);
        if (lane == 0) { s_red[16 + wid] = ra; s_red[18 + wid] = rb; }
    }
    __syncthreads();

    if (t == 0) {
        float sa = 0.0f, sb = 0.0f;
#pragma unroll
        for (int w = 0; w < 8; w++) { sa += s_red[w]; sb += s_red[8 + w]; }
        sa += s_red[16] + s_red[17];
        sb += s_red[18] + s_red[19];
        float ua = u_a[b], ub = u_b[b];
        float la  = logf(ua) - log1pf(-ua);
        float lbv = logf(ub) - log1pf(-ub);
        outp[(size_t)b * 2050 + 2048] = sigmoidf_((sa + la)  / TAUF);
        outp[(size_t)b * 2050 + 2049] = sigmoidf_((sb + lbv) / TAUF);
    }
}

// ---------------------------------------------------------------------------
extern "C" void kernel_launch(void* const* d_in, const int* in_sizes, int n_in,
                              void* d_out, int out_size)
{
    const float* x      = (const float*)d_in[0];
    const float* h      = (const float*)d_in[1];
    const float* c      = (const float*)d_in[2];
    const float* memory = (const float*)d_in[3];
    const float* u_gs   = (const float*)d_in[4];
    const float* u_a    = (const float*)d_in[5];
    const float* u_b    = (const float*)d_in[6];
    const float* W_i    = (const float*)d_in[7];
    const float* b_i    = (const float*)d_in[8];
    const float* W_f    = (const float*)d_in[9];
    const float* b_f    = (const float*)d_in[10];
    const float* W_o    = (const float*)d_in[11];
    const float* b_o    = (const float*)d_in[12];
    const float* W_cand = (const float*)d_in[13];
    const float* b_cand = (const float*)d_in[14];
    const float* W_m    = (const float*)d_in[15];
    const float* b_m    = (const float*)d_in[16];
    const float* w_a_h  = (const float*)d_in[17];
    const float* w_a_x  = (const float*)d_in[18];
    const float* w_a_r  = (const float*)d_in[19];
    const float* w_b_h  = (const float*)d_in[20];
    const float* w_b_x  = (const float*)d_in[21];
    const float* w_b_r  = (const float*)d_in[22];
    float* out = (float*)d_out;

    dim3 gg(HH / BN, BB / BM);   // (8, 64)

    // Pass 1: three gate GEMMs (independent)
    gemm_act<<<gg, 256>>>(x, h, c,       W_i,    b_i,    3072, 0, out);
    gemm_act<<<gg, 256>>>(x, h, c,       W_f,    b_f,    3072, 1, out);
    gemm_act<<<gg, 256>>>(x, h, nullptr, W_cand, b_cand, 2048, 2, out);

    // Pass 2: c_new elementwise
    cnew_kernel<<<(BHsz / 4) / 256, 256>>>(c, out);

    // Pass 3: o-gate GEMM fused with h_new
    gemm_act<<<gg, 256>>>(x, h, nullptr, W_o, b_o, 3072, 3, out);

    // Pass 4: micro GEMM
    micro_gemm<<<BB / 64, 256>>>(W_m, b_m);

    // Pass 5: attention + alpha/beta
    finalize_kernel<<<BB, 256>>>(x, memory, u_gs, u_a, u_b,
                                 w_a_h, w_a_x, w_a_r,
                                 w_b_h, w_b_x, w_b_r, out);
}

// round 9
// speedup vs baseline: 2.5524x; 2.5524x over previous
#include <cuda_runtime.h>
#include <cuda_bf16.h>
#include <math.h>
#include <stdint.h>

#define BB   8192
#define HH   1024
#define TAUF 1.0f
#define BHsz (BB * HH)

typedef __nv_bfloat16 bf16;

// ---------------- scratch (static device arrays; no allocs) ----------------
__device__ bf16 g_A_hi[(size_t)BB * 3072];     // [x|h|c] bf16 hi
__device__ bf16 g_A_lo[(size_t)BB * 3072];
__device__ bf16 g_c2_hi[BHsz];                 // c_new split
__device__ bf16 g_c2_lo[BHsz];
__device__ bf16 g_Wi_hi[(size_t)3072 * 1024];  // weights, natural [K][N] layout
__device__ bf16 g_Wi_lo[(size_t)3072 * 1024];
__device__ bf16 g_Wf_hi[(size_t)3072 * 1024];
__device__ bf16 g_Wf_lo[(size_t)3072 * 1024];
__device__ bf16 g_Wo_hi[(size_t)3072 * 1024];
__device__ bf16 g_Wo_lo[(size_t)3072 * 1024];
__device__ bf16 g_Wc_hi[(size_t)2048 * 1024];
__device__ bf16 g_Wc_lo[(size_t)2048 * 1024];
__device__ float g_if[(size_t)BB * 2048];      // sigmoid(i) | sigmoid(f)
__device__ float g_cand[BHsz];                 // tanh(cand)
__device__ float g_cnew[BHsz];
__device__ float g_hnew[BHsz];
__device__ float g_micro[BB * 64];

__device__ __forceinline__ float sigmoidf_(float v) { return 1.0f / (1.0f + expf(-v)); }

__device__ __forceinline__ uint32_t smem_to_u32(const void* p) {
    uint32_t a;
    asm("{ .reg .u64 t; cvta.to.shared.u64 t, %1; cvt.u32.u64 %0, t; }" : "=r"(a) : "l"(p));
    return a;
}
__device__ __forceinline__ void cp16(uint32_t saddr, const void* g) {
    asm volatile("cp.async.cg.shared.global [%0], [%1], 16;" :: "r"(saddr), "l"(g));
}
#define CP_COMMIT() asm volatile("cp.async.commit_group;")
#define CP_WAIT(n)  asm volatile("cp.async.wait_group %0;" :: "n"(n))

__device__ __forceinline__ void ldsm_x4(uint32_t* r, uint32_t a) {
    asm volatile("ldmatrix.sync.aligned.m8n8.x4.shared.b16 {%0,%1,%2,%3}, [%4];"
                 : "=r"(r[0]), "=r"(r[1]), "=r"(r[2]), "=r"(r[3]) : "r"(a));
}
__device__ __forceinline__ void ldsm_x4_t(uint32_t* r, uint32_t a) {
    asm volatile("ldmatrix.sync.aligned.m8n8.x4.trans.shared.b16 {%0,%1,%2,%3}, [%4];"
                 : "=r"(r[0]), "=r"(r[1]), "=r"(r[2]), "=r"(r[3]) : "r"(a));
}
__device__ __forceinline__ void mma_bf16(float* d, const uint32_t* a, const uint32_t* b) {
    asm volatile("mma.sync.aligned.m16n8k16.row.col.f32.bf16.bf16.f32 "
                 "{%0,%1,%2,%3}, {%4,%5,%6,%7}, {%8,%9}, {%0,%1,%2,%3};"
                 : "+f"(d[0]), "+f"(d[1]), "+f"(d[2]), "+f"(d[3])
                 : "r"(a[0]), "r"(a[1]), "r"(a[2]), "r"(a[3]), "r"(b[0]), "r"(b[1]));
}

__device__ __forceinline__ uint32_t pack2(bf16 a, bf16 b) {
    __nv_bfloat162 t; t.x = a; t.y = b;
    return *reinterpret_cast<uint32_t*>(&t);
}
__device__ __forceinline__ void split_bf16(float v, bf16& hi, bf16& lo) {
    hi = __float2bfloat16(v);
    lo = __float2bfloat16(v - __bfloat162float(hi));
}

// ---------------- convert A = [x|h|c] -> bf16 hi/lo ----------------
__global__ __launch_bounds__(256) void convA(
    const float* __restrict__ x, const float* __restrict__ h, const float* __restrict__ c)
{
    size_t e = ((size_t)blockIdx.x * 256 + threadIdx.x) * 4;
    size_t row = e / 3072;
    int col = (int)(e % 3072);
    const float* src = (col < 1024) ? x + row * 1024 + col
                     : (col < 2048) ? h + row * 1024 + (col - 1024)
                                    : c + row * 1024 + (col - 2048);
    float4 v = *(const float4*)src;
    bf16 h0, l0, h1, l1, h2, l2, h3, l3;
    split_bf16(v.x, h0, l0); split_bf16(v.y, h1, l1);
    split_bf16(v.z, h2, l2); split_bf16(v.w, h3, l3);
    *(uint2*)(g_A_hi + e) = make_uint2(pack2(h0, h1), pack2(h2, h3));
    *(uint2*)(g_A_lo + e) = make_uint2(pack2(l0, l1), pack2(l2, l3));
}

// ---------------- convert W (elementwise, natural layout) ----------------
__global__ __launch_bounds__(256) void convW(const float* __restrict__ W, int which)
{
    bf16 *hi, *lo;
    if (which == 0)      { hi = g_Wi_hi; lo = g_Wi_lo; }
    else if (which == 1) { hi = g_Wf_hi; lo = g_Wf_lo; }
    else if (which == 2) { hi = g_Wo_hi; lo = g_Wo_lo; }
    else                 { hi = g_Wc_hi; lo = g_Wc_lo; }
    size_t e = ((size_t)blockIdx.x * 256 + threadIdx.x) * 4;
    float4 v = *(const float4*)(W + e);
    bf16 h0, l0, h1, l1, h2, l2, h3, l3;
    split_bf16(v.x, h0, l0); split_bf16(v.y, h1, l1);
    split_bf16(v.z, h2, l2); split_bf16(v.w, h3, l3);
    *(uint2*)(hi + e) = make_uint2(pack2(h0, h1), pack2(h2, h3));
    *(uint2*)(lo + e) = make_uint2(pack2(l0, l1), pack2(l2, l3));
}

// ---------------- HMMA split-bf16 GEMM ----------------
// Tiles: CTA 128x128, BK=32, 256 threads, warp tile 64x32.
// smem (bf16 elems): A [128][40] (pad), B [32][136] (pad), hi+lo, double-buffered.
#define OFF_AHI 0
#define OFF_ALO 10240
#define OFF_BHI 20480
#define OFF_BLO 29184
#define STAGE   37888
#define SMEM_SZ (2 * STAGE)

// mode 0: i|f (K=3072, N=2048 -> g_if)
// mode 1: cand (K=2048 -> g_cand)
// mode 2: o (K=3072, k>=2048 from c_new split; h_new -> g_hnew + out[:, :1024])
__global__ __launch_bounds__(256) void gemm_hmma(
    int K, int mode,
    const float* __restrict__ bias_a, const float* __restrict__ bias_b,
    float* __restrict__ outp)
{
    extern __shared__ char smem[];
    const uint32_t sbase = smem_to_u32(smem);
    const int tid = threadIdx.x, lane = tid & 31, wid = tid >> 5;
    const int warp_m = wid >> 2, warp_n = wid & 3;
    const int bn = blockIdx.x * 128, bm = blockIdx.y * 128;

    const bf16 *Whi, *Wlo; int bcol;
    if (mode == 0) {
        if (bn < 1024) { Whi = g_Wi_hi; Wlo = g_Wi_lo; bcol = bn; }
        else           { Whi = g_Wf_hi; Wlo = g_Wf_lo; bcol = bn - 1024; }
    } else if (mode == 1) { Whi = g_Wc_hi; Wlo = g_Wc_lo; bcol = bn; }
    else                  { Whi = g_Wo_hi; Wlo = g_Wo_lo; bcol = bn; }

    // copy-chunk coordinates
    const int arA0 = tid >> 2, achA = (tid & 3) * 8;          // + i*64 rows
    const int brB0 = tid >> 4, bchB = (tid & 15) * 8;         // + i*16 rows

    // ldmatrix lane offsets
    const int rowL = (lane & 7) + ((lane >> 3) & 1) * 8;
    const int colL = (lane >> 4) * 8;

    float acc[4][4][4];
#pragma unroll
    for (int i = 0; i < 4; i++)
#pragma unroll
        for (int j = 0; j < 4; j++)
#pragma unroll
            for (int q = 0; q < 4; q++) acc[i][j][q] = 0.0f;

    const int nT = K / 32;

#define COPY_TILE(stg, kt_) do {                                                   \
        int k0_ = (kt_) * 32;                                                      \
        const bf16 *ah_, *al_; int strA_, kof_;                                    \
        if (mode == 2 && k0_ >= 2048) { ah_ = g_c2_hi; al_ = g_c2_lo; strA_ = 1024; kof_ = k0_ - 2048; } \
        else                          { ah_ = g_A_hi;  al_ = g_A_lo;  strA_ = 3072; kof_ = k0_; }        \
        uint32_t sb_ = sbase + (stg) * STAGE;                                      \
        _Pragma("unroll")                                                          \
        for (int i_ = 0; i_ < 2; i_++) {                                           \
            int r_ = arA0 + i_ * 64;                                               \
            size_t g_ = (size_t)(bm + r_) * strA_ + kof_ + achA;                   \
            uint32_t so_ = sb_ + (r_ * 40 + achA) * 2;                             \
            cp16(so_ + OFF_AHI, ah_ + g_);                                         \
            cp16(so_ + OFF_ALO, al_ + g_);                                         \
        }                                                                          \
        _Pragma("unroll")                                                          \
        for (int i_ = 0; i_ < 2; i_++) {                                           \
            int r_ = brB0 + i_ * 16;                                               \
            size_t g_ = (size_t)(k0_ + r_) * 1024 + bcol + bchB;                   \
            uint32_t so_ = sb_ + (r_ * 136 + bchB) * 2;                            \
            cp16(so_ + OFF_BHI, Whi + g_);                                         \
            cp16(so_ + OFF_BLO, Wlo + g_);                                         \
        }                                                                          \
    } while (0)

    COPY_TILE(0, 0);
    CP_COMMIT();

    int buf = 0;
    for (int kt = 0; kt < nT; kt++) {
        if (kt + 1 < nT) { COPY_TILE(buf ^ 1, kt + 1); CP_COMMIT(); CP_WAIT(1); }
        else             { CP_WAIT(0); }
        __syncthreads();

        uint32_t sb = sbase + buf * STAGE;
#pragma unroll
        for (int ks = 0; ks < 2; ks++) {
            uint32_t bhi[8], blo[8];
#pragma unroll
            for (int nt = 0; nt < 2; nt++) {
                uint32_t ad = sb + OFF_BHI +
                    (uint32_t)((ks * 16 + rowL) * 136 + warp_n * 32 + nt * 16 + colL) * 2;
                ldsm_x4_t(&bhi[nt * 4], ad);
                ldsm_x4_t(&blo[nt * 4], ad + (OFF_BLO - OFF_BHI));
            }
#pragma unroll
            for (int mi = 0; mi < 4; mi++) {
                uint32_t ahi[4], alo[4];
                uint32_t ad = sb + OFF_AHI +
                    (uint32_t)((warp_m * 64 + mi * 16 + rowL) * 40 + ks * 16 + colL) * 2;
                ldsm_x4(ahi, ad);
                ldsm_x4(alo, ad + (OFF_ALO - OFF_AHI));
#pragma unroll
                for (int ni = 0; ni < 4; ni++) {
                    uint32_t* bh = &bhi[(ni >> 1) * 4 + (ni & 1) * 2];
                    uint32_t* bl = &blo[(ni >> 1) * 4 + (ni & 1) * 2];
                    mma_bf16(acc[mi][ni], ahi, bh);
                    mma_bf16(acc[mi][ni], ahi, bl);
                    mma_bf16(acc[mi][ni], alo, bh);
                }
            }
        }
        __syncthreads();
        buf ^= 1;
    }

    // Epilogue
    const float* biasp = ((mode == 0 && bn >= 1024) ? bias_b : bias_a) + bcol;
#pragma unroll
    for (int mi = 0; mi < 4; mi++) {
        int row0 = bm + warp_m * 64 + mi * 16 + (lane >> 2);
#pragma unroll
        for (int ni = 0; ni < 4; ni++) {
            int cl = warp_n * 32 + ni * 8 + (lane & 3) * 2;
            float b0 = biasp[cl], b1 = biasp[cl + 1];
            float* a = acc[mi][ni];
#pragma unroll
            for (int half = 0; half < 2; half++) {
                int row = row0 + half * 8;
                float v0 = a[half * 2 + 0] + b0;
                float v1 = a[half * 2 + 1] + b1;
                if (mode == 0) {
                    *(float2*)&g_if[(size_t)row * 2048 + bn + cl] =
                        make_float2(sigmoidf_(v0), sigmoidf_(v1));
                } else if (mode == 1) {
                    *(float2*)&g_cand[(size_t)row * 1024 + bn + cl] =
                        make_float2(tanhf(v0), tanhf(v1));
                } else {
                    float2 cn = *(const float2*)&g_cnew[(size_t)row * 1024 + bn + cl];
                    float hn0 = sigmoidf_(v0) * tanhf(cn.x);
                    float hn1 = sigmoidf_(v1) * tanhf(cn.y);
                    *(float2*)&g_hnew[(size_t)row * 1024 + bn + cl] = make_float2(hn0, hn1);
                    *(float2*)&outp[(size_t)row * 2050 + bn + cl] = make_float2(hn0, hn1);
                }
            }
        }
    }
#undef COPY_TILE
}

// ---------------- c_new = f*c + i*cand (+ bf16 split for o-gate) ----------------
__global__ __launch_bounds__(256) void cnew_kernel(
    const float* __restrict__ c, float* __restrict__ outp)
{
    size_t idx = ((size_t)blockIdx.x * 256 + threadIdx.x) * 4;
    size_t row = idx >> 10;
    int col = (int)(idx & 1023);
    float4 gi = *(const float4*)&g_if[row * 2048 + col];
    float4 gf = *(const float4*)&g_if[row * 2048 + 1024 + col];
    float4 gp = *(const float4*)&g_cand[idx];
    float4 cv = *(const float4*)&c[idx];
    float4 cn;
    cn.x = gf.x * cv.x + gi.x * gp.x;
    cn.y = gf.y * cv.y + gi.y * gp.y;
    cn.z = gf.z * cv.z + gi.z * gp.z;
    cn.w = gf.w * cv.w + gi.w * gp.w;
    *(float4*)&g_cnew[idx] = cn;
    float* doo = &outp[row * 2050 + 1024 + col];
    *(float2*)&doo[0] = make_float2(cn.x, cn.y);
    *(float2*)&doo[2] = make_float2(cn.z, cn.w);
    bf16 h0, l0, h1, l1, h2, l2, h3, l3;
    split_bf16(cn.x, h0, l0); split_bf16(cn.y, h1, l1);
    split_bf16(cn.z, h2, l2); split_bf16(cn.w, h3, l3);
    *(uint2*)(g_c2_hi + idx) = make_uint2(pack2(h0, h1), pack2(h2, h3));
    *(uint2*)(g_c2_lo + idx) = make_uint2(pack2(l0, l1), pack2(l2, l3));
}

// ---------------- micro = h_new @ W_m + b_m ----------------
__global__ __launch_bounds__(256) void micro_gemm(
    const float* __restrict__ Wm, const float* __restrict__ bmv)
{
    __shared__ float sH[64][33];
    __shared__ float sW[32][64];
    const int bm0 = blockIdx.x * 64;
    const int tid = threadIdx.x;
    const int tx = tid & 15, ty = tid >> 4;

    float acc[4][4];
#pragma unroll
    for (int i = 0; i < 4; i++)
#pragma unroll
        for (int j = 0; j < 4; j++) acc[i][j] = 0.0f;

    for (int k0 = 0; k0 < 1024; k0 += 32) {
#pragma unroll
        for (int i = 0; i < 2; i++) {
            int idx = tid + i * 256;
            int r = idx >> 3, c4 = (idx & 7) * 4;
            float4 v = *(const float4*)&g_hnew[(size_t)(bm0 + r) * 1024 + k0 + c4];
            sH[r][c4 + 0] = v.x; sH[r][c4 + 1] = v.y;
            sH[r][c4 + 2] = v.z; sH[r][c4 + 3] = v.w;
        }
#pragma unroll
        for (int i = 0; i < 2; i++) {
            int idx = tid + i * 256;
            int r = idx >> 4, c4 = (idx & 15) * 4;
            *(float4*)&sW[r][c4] = *(const float4*)&Wm[(size_t)(k0 + r) * 64 + c4];
        }
        __syncthreads();
#pragma unroll
        for (int kk = 0; kk < 32; kk++) {
            float a[4];
#pragma unroll
            for (int i = 0; i < 4; i++) a[i] = sH[ty * 4 + i][kk];
            float4 b4 = *(const float4*)&sW[kk][tx * 4];
            float b[4] = {b4.x, b4.y, b4.z, b4.w};
#pragma unroll
            for (int i = 0; i < 4; i++)
#pragma unroll
                for (int j = 0; j < 4; j++)
                    acc[i][j] = fmaf(a[i], b[j], acc[i][j]);
        }
        __syncthreads();
    }
    float4 bb = *(const float4*)&bmv[tx * 4];
    float bv[4] = {bb.x, bb.y, bb.z, bb.w};
#pragma unroll
    for (int i = 0; i < 4; i++) {
        int row = bm0 + ty * 4 + i;
        *(float4*)&g_micro[(size_t)row * 64 + tx * 4] =
            make_float4(acc[i][0] + bv[0], acc[i][1] + bv[1],
                        acc[i][2] + bv[2], acc[i][3] + bv[3]);
    }
}

// ---------------- finalize ----------------
__device__ __forceinline__ float warpred(float v) {
#pragma unroll
    for (int o = 16; o > 0; o >>= 1) v += __shfl_down_sync(0xffffffffu, v, o);
    return v;
}

__global__ __launch_bounds__(256) void finalize_kernel(
    const float* __restrict__ x,
    const float* __restrict__ mem,
    const float* __restrict__ u_gs,
    const float* __restrict__ u_a, const float* __restrict__ u_b,
    const float* __restrict__ w_a_h, const float* __restrict__ w_a_x,
    const float* __restrict__ w_a_r,
    const float* __restrict__ w_b_h, const float* __restrict__ w_b_x,
    const float* __restrict__ w_b_r,
    float* __restrict__ outp)
{
    __shared__ float s_micro[64];
    __shared__ float s_part[256];
    __shared__ float s_attn[16];
    __shared__ float s_red[20];

    const int b = blockIdx.x;
    const int t = threadIdx.x;
    const int lane = t & 31, wid = t >> 5;

    const float* hrow = g_hnew + (size_t)b * 1024;
    const float* xrow = x + (size_t)b * 1024;
    const float* mrow = mem + (size_t)b * 1024;

    {
        float4 h4 = *(const float4*)&hrow[t * 4];
        float4 x4 = *(const float4*)&xrow[t * 4];
        float4 ah = *(const float4*)&w_a_h[t * 4];
        float4 ax = *(const float4*)&w_a_x[t * 4];
        float4 bh = *(const float4*)&w_b_h[t * 4];
        float4 bx = *(const float4*)&w_b_x[t * 4];
        float pa = h4.x*ah.x + h4.y*ah.y + h4.z*ah.z + h4.w*ah.w
                 + x4.x*ax.x + x4.y*ax.y + x4.z*ax.z + x4.w*ax.w;
        float pb = h4.x*bh.x + h4.y*bh.y + h4.z*bh.z + h4.w*bh.w
                 + x4.x*bx.x + x4.y*bx.y + x4.z*bx.z + x4.w*bx.w;
        pa = warpred(pa); pb = warpred(pb);
        if (lane == 0) { s_red[wid] = pa; s_red[8 + wid] = pb; }
    }
    if (t < 16)
        *(float4*)&s_micro[t * 4] = *(const float4*)&g_micro[(size_t)b * 64 + t * 4];
    __syncthreads();

    {
        int m = t >> 4, q = t & 15;
        float4 m4 = *(const float4*)&mrow[m * 64 + q * 4];
        float4 u4 = *(const float4*)&s_micro[q * 4];
        s_part[t] = m4.x*u4.x + m4.y*u4.y + m4.z*u4.z + m4.w*u4.w;
    }
    __syncthreads();

    if (t < 16) {
        float lg = 0.0f;
#pragma unroll
        for (int q = 0; q < 16; q++) lg += s_part[t * 16 + q];
        float u = u_gs[(size_t)b * 16 + t];
        lg += -logf(-logf(u));
        lg /= TAUF;
        float mx = lg;
#pragma unroll
        for (int o = 8; o > 0; o >>= 1)
            mx = fmaxf(mx, __shfl_xor_sync(0xffffu, mx, o));
        float e = expf(lg - mx);
        float s = e;
#pragma unroll
        for (int o = 8; o > 0; o >>= 1)
            s += __shfl_xor_sync(0xffffu, s, o);
        s_attn[t] = e / s;
    }
    __syncthreads();

    if (t < 64) {
        float sv = 0.0f;
#pragma unroll
        for (int m = 0; m < 16; m++) sv += mrow[m * 64 + t] * s_attn[m];
        sv += 1.0f;
        float ra = sv * w_a_r[t];
        float rb = sv * w_b_r[t];
        ra = warpred(ra); rb = warpred(rb);
        if (lane == 0) { s_red[16 + wid] = ra; s_red[18 + wid] = rb; }
    }
    __syncthreads();

    if (t == 0) {
        float sa = 0.0f, sb = 0.0f;
#pragma unroll
        for (int w = 0; w < 8; w++) { sa += s_red[w]; sb += s_red[8 + w]; }
        sa += s_red[16] + s_red[17];
        sb += s_red[18] + s_red[19];
        float ua = u_a[b], ub = u_b[b];
        float la  = logf(ua) - log1pf(-ua);
        float lbv = logf(ub) - log1pf(-ub);
        outp[(size_t)b * 2050 + 2048] = sigmoidf_((sa + la)  / TAUF);
        outp[(size_t)b * 2050 + 2049] = sigmoidf_((sb + lbv) / TAUF);
    }
}

// ---------------------------------------------------------------------------
extern "C" void kernel_launch(void* const* d_in, const int* in_sizes, int n_in,
                              void* d_out, int out_size)
{
    const float* x      = (const float*)d_in[0];
    const float* h      = (const float*)d_in[1];
    const float* c      = (const float*)d_in[2];
    const float* memory = (const float*)d_in[3];
    const float* u_gs   = (const float*)d_in[4];
    const float* u_a    = (const float*)d_in[5];
    const float* u_b    = (const float*)d_in[6];
    const float* W_i    = (const float*)d_in[7];
    const float* b_i    = (const float*)d_in[8];
    const float* W_f    = (const float*)d_in[9];
    const float* b_f    = (const float*)d_in[10];
    const float* W_o    = (const float*)d_in[11];
    const float* b_o    = (const float*)d_in[12];
    const float* W_cand = (const float*)d_in[13];
    const float* b_cand = (const float*)d_in[14];
    const float* W_m    = (const float*)d_in[15];
    const float* b_m    = (const float*)d_in[16];
    const float* w_a_h  = (const float*)d_in[17];
    const float* w_a_x  = (const float*)d_in[18];
    const float* w_a_r  = (const float*)d_in[19];
    const float* w_b_h  = (const float*)d_in[20];
    const float* w_b_x  = (const float*)d_in[21];
    const float* w_b_r  = (const float*)d_in[22];
    float* out = (float*)d_out;

    // Idempotent, not a stream op — safe to call every time (no static guards).
    cudaFuncSetAttribute(gemm_hmma, cudaFuncAttributeMaxDynamicSharedMemorySize, SMEM_SZ);

    // conversions
    convA<<<(BB * 3072 / 4) / 256, 256>>>(x, h, c);
    convW<<<(3072 * 1024 / 4) / 256, 256>>>(W_i,    0);
    convW<<<(3072 * 1024 / 4) / 256, 256>>>(W_f,    1);
    convW<<<(3072 * 1024 / 4) / 256, 256>>>(W_o,    2);
    convW<<<(2048 * 1024 / 4) / 256, 256>>>(W_cand, 3);

    // gate GEMMs
    gemm_hmma<<<dim3(16, 64), 256, SMEM_SZ>>>(3072, 0, b_i, b_f, out);       // i|f
    gemm_hmma<<<dim3(8, 64), 256, SMEM_SZ>>>(2048, 1, b_cand, nullptr, out); // cand

    cnew_kernel<<<(BHsz / 4) / 256, 256>>>(c, out);

    gemm_hmma<<<dim3(8, 64), 256, SMEM_SZ>>>(3072, 2, b_o, nullptr, out);    // o + h_new

    micro_gemm<<<BB / 64, 256>>>(W_m, b_m);
    finalize_kernel<<<BB, 256>>>(x, memory, u_gs, u_a, u_b,
                                 w_a_h, w_a_x, w_a_r,
                                 w_b_h, w_b_x, w_b_r, out);
}

// round 12
// speedup vs baseline: 3.0966x; 1.2132x over previous
#include <cuda_runtime.h>
#include <cuda_fp16.h>
#include <math.h>
#include <stdint.h>

#define BB   8192
#define HH   1024
#define TAUF 1.0f
#define BHsz (BB * HH)

typedef __half fp16;

// ---------------- scratch (static device arrays; no allocs) ----------------
__device__ fp16 g_A_hi[(size_t)BB * 3072];     // [x|h|c] fp16 hi
__device__ fp16 g_A_lo[(size_t)BB * 3072];     // fp16 residual
__device__ fp16 g_c2_hi[BHsz];                 // c_new split
__device__ fp16 g_c2_lo[BHsz];
__device__ fp16 g_Wi[(size_t)3072 * 1024];     // weights, single fp16, [K][N]
__device__ fp16 g_Wf[(size_t)3072 * 1024];
__device__ fp16 g_Wo[(size_t)3072 * 1024];
__device__ fp16 g_Wc[(size_t)2048 * 1024];
__device__ float g_if[(size_t)BB * 2048];      // sigmoid(i) | sigmoid(f)
__device__ float g_cand[BHsz];                 // tanh(cand)
__device__ float g_cnew[BHsz];
__device__ float g_hnew[BHsz];
__device__ float g_micro[BB * 64];

__device__ __forceinline__ float sigmoidf_(float v) { return 1.0f / (1.0f + expf(-v)); }

__device__ __forceinline__ uint32_t smem_to_u32(const void* p) {
    uint32_t a;
    asm("{ .reg .u64 t; cvta.to.shared.u64 t, %1; cvt.u32.u64 %0, t; }" : "=r"(a) : "l"(p));
    return a;
}
__device__ __forceinline__ void cp16cp(uint32_t saddr, const void* g) {
    asm volatile("cp.async.cg.shared.global [%0], [%1], 16;" :: "r"(saddr), "l"(g));
}
#define CP_COMMIT() asm volatile("cp.async.commit_group;")
#define CP_WAIT(n)  asm volatile("cp.async.wait_group %0;" :: "n"(n))

__device__ __forceinline__ void ldsm_x4(uint32_t* r, uint32_t a) {
    asm volatile("ldmatrix.sync.aligned.m8n8.x4.shared.b16 {%0,%1,%2,%3}, [%4];"
                 : "=r"(r[0]), "=r"(r[1]), "=r"(r[2]), "=r"(r[3]) : "r"(a));
}
__device__ __forceinline__ void ldsm_x4_t(uint32_t* r, uint32_t a) {
    asm volatile("ldmatrix.sync.aligned.m8n8.x4.trans.shared.b16 {%0,%1,%2,%3}, [%4];"
                 : "=r"(r[0]), "=r"(r[1]), "=r"(r[2]), "=r"(r[3]) : "r"(a));
}
__device__ __forceinline__ void mma_fp16(float* d, const uint32_t* a, const uint32_t* b) {
    asm volatile("mma.sync.aligned.m16n8k16.row.col.f32.f16.f16.f32 "
                 "{%0,%1,%2,%3}, {%4,%5,%6,%7}, {%8,%9}, {%0,%1,%2,%3};"
                 : "+f"(d[0]), "+f"(d[1]), "+f"(d[2]), "+f"(d[3])
                 : "r"(a[0]), "r"(a[1]), "r"(a[2]), "r"(a[3]), "r"(b[0]), "r"(b[1]));
}

__device__ __forceinline__ uint32_t pack2h(fp16 a, fp16 b) {
    __half2 t; t.x = a; t.y = b;
    return *reinterpret_cast<uint32_t*>(&t);
}
__device__ __forceinline__ void split_fp16(float v, fp16& hi, fp16& lo) {
    hi = __float2half(v);
    lo = __float2half(v - __half2float(hi));
}

// ---------------- convert A = [x|h|c] -> fp16 hi/lo ----------------
__global__ __launch_bounds__(256) void convA(
    const float* __restrict__ x, const float* __restrict__ h, const float* __restrict__ c)
{
    size_t e = ((size_t)blockIdx.x * 256 + threadIdx.x) * 4;
    size_t row = e / 3072;
    int col = (int)(e % 3072);
    const float* src = (col < 1024) ? x + row * 1024 + col
                     : (col < 2048) ? h + row * 1024 + (col - 1024)
                                    : c + row * 1024 + (col - 2048);
    float4 v = *(const float4*)src;
    fp16 h0, l0, h1, l1, h2, l2, h3, l3;
    split_fp16(v.x, h0, l0); split_fp16(v.y, h1, l1);
    split_fp16(v.z, h2, l2); split_fp16(v.w, h3, l3);
    *(uint2*)(g_A_hi + e) = make_uint2(pack2h(h0, h1), pack2h(h2, h3));
    *(uint2*)(g_A_lo + e) = make_uint2(pack2h(l0, l1), pack2h(l2, l3));
}

// ---------------- convert W (single fp16, natural layout) ----------------
__global__ __launch_bounds__(256) void convW(const float* __restrict__ W, int which)
{
    fp16* dst;
    if (which == 0)      dst = g_Wi;
    else if (which == 1) dst = g_Wf;
    else if (which == 2) dst = g_Wo;
    else                 dst = g_Wc;
    size_t e = ((size_t)blockIdx.x * 256 + threadIdx.x) * 4;
    float4 v = *(const float4*)(W + e);
    *(uint2*)(dst + e) = make_uint2(
        pack2h(__float2half(v.x), __float2half(v.y)),
        pack2h(__float2half(v.z), __float2half(v.w)));
}

// ---------------- HMMA fp16 2-pass GEMM ----------------
// CTA tile 128x256, BK=32, 256 threads (8 warps), warp tile 64x64.
// smem (fp16): A_hi [128][40], A_lo [128][40], B [32][264]; double-buffered.
#define OFF_AHI 0
#define OFF_ALO 10240
#define OFF_B   20480
#define STAGE   37376
#define SMEM_SZ (2 * STAGE)

// mode 0: i|f (K=3072, N=2048 -> g_if)
// mode 1: cand (K=2048 -> g_cand)
// mode 2: o (K=3072, k>=2048 from c_new split; h_new -> g_hnew + out[:, :1024])
__global__ __launch_bounds__(256) void gemm_hmma(
    int K, int mode,
    const float* __restrict__ bias_a, const float* __restrict__ bias_b,
    float* __restrict__ outp)
{
    extern __shared__ char smem[];
    const uint32_t sbase = smem_to_u32(smem);
    const int tid = threadIdx.x, lane = tid & 31, wid = tid >> 5;
    const int warp_m = wid >> 2, warp_n = wid & 3;
    const int bn = blockIdx.x * 256, bm = blockIdx.y * 128;

    const fp16* W; int bcol;
    if (mode == 0) {
        if (bn < 1024) { W = g_Wi; bcol = bn; }
        else           { W = g_Wf; bcol = bn - 1024; }
    } else if (mode == 1) { W = g_Wc; bcol = bn; }
    else                  { W = g_Wo; bcol = bn; }

    // copy-chunk coordinates
    const int arA0 = tid >> 2, achA = (tid & 3) * 8;     // A: rows 0..63 (+64), 8-elem chunks
    const int brB0 = tid >> 5, bchB = (tid & 31) * 8;    // B: rows 0..7 (+8 per iter)

    // ldmatrix lane offsets
    const int rowL = (lane & 7) + ((lane >> 3) & 1) * 8;
    const int colL = (lane >> 4) * 8;

    float acc[4][8][4];
#pragma unroll
    for (int i = 0; i < 4; i++)
#pragma unroll
        for (int j = 0; j < 8; j++)
#pragma unroll
            for (int q = 0; q < 4; q++) acc[i][j][q] = 0.0f;

    const int nT = K / 32;

#define COPY_TILE(stg, kt_) do {                                                   \
        int k0_ = (kt_) * 32;                                                      \
        const fp16 *ah_, *al_; int strA_, kof_;                                    \
        if (mode == 2 && k0_ >= 2048) { ah_ = g_c2_hi; al_ = g_c2_lo; strA_ = 1024; kof_ = k0_ - 2048; } \
        else                          { ah_ = g_A_hi;  al_ = g_A_lo;  strA_ = 3072; kof_ = k0_; }        \
        uint32_t sb_ = sbase + (stg) * STAGE;                                      \
        _Pragma("unroll")                                                          \
        for (int i_ = 0; i_ < 2; i_++) {                                           \
            int r_ = arA0 + i_ * 64;                                               \
            size_t g_ = (size_t)(bm + r_) * strA_ + kof_ + achA;                   \
            uint32_t so_ = sb_ + (r_ * 40 + achA) * 2;                             \
            cp16cp(so_ + OFF_AHI, ah_ + g_);                                       \
            cp16cp(so_ + OFF_ALO, al_ + g_);                                       \
        }                                                                          \
        _Pragma("unroll")                                                          \
        for (int i_ = 0; i_ < 4; i_++) {                                           \
            int r_ = brB0 + i_ * 8;                                                \
            size_t g_ = (size_t)(k0_ + r_) * 1024 + bcol + bchB;                   \
            uint32_t so_ = sb_ + OFF_B + (r_ * 264 + bchB) * 2;                    \
            cp16cp(so_, W + g_);                                                   \
        }                                                                          \
    } while (0)

    COPY_TILE(0, 0);
    CP_COMMIT();

    int buf = 0;
    for (int kt = 0; kt < nT; kt++) {
        if (kt + 1 < nT) { COPY_TILE(buf ^ 1, kt + 1); CP_COMMIT(); CP_WAIT(1); }
        else             { CP_WAIT(0); }
        __syncthreads();

        uint32_t sb = sbase + buf * STAGE;
#pragma unroll
        for (int ks = 0; ks < 2; ks++) {
            uint32_t bfr[16];
#pragma unroll
            for (int nt = 0; nt < 4; nt++) {
                uint32_t ad = sb + OFF_B +
                    (uint32_t)((ks * 16 + rowL) * 264 + warp_n * 64 + nt * 16 + colL) * 2;
                ldsm_x4_t(&bfr[nt * 4], ad);
            }
#pragma unroll
            for (int mi = 0; mi < 4; mi++) {
                uint32_t ahi[4], alo[4];
                uint32_t ad = sb + OFF_AHI +
                    (uint32_t)((warp_m * 64 + mi * 16 + rowL) * 40 + ks * 16 + colL) * 2;
                ldsm_x4(ahi, ad);
                ldsm_x4(alo, ad + (OFF_ALO - OFF_AHI));
#pragma unroll
                for (int ni = 0; ni < 8; ni++) {
                    uint32_t* b = &bfr[(ni >> 1) * 4 + (ni & 1) * 2];
                    mma_fp16(acc[mi][ni], ahi, b);
                    mma_fp16(acc[mi][ni], alo, b);
                }
            }
        }
        __syncthreads();
        buf ^= 1;
    }

    // Epilogue
    const float* biasp = ((mode == 0 && bn >= 1024) ? bias_b : bias_a) + bcol;
#pragma unroll
    for (int mi = 0; mi < 4; mi++) {
        int row0 = bm + warp_m * 64 + mi * 16 + (lane >> 2);
#pragma unroll
        for (int ni = 0; ni < 8; ni++) {
            int cl = warp_n * 64 + ni * 8 + (lane & 3) * 2;
            float b0 = biasp[cl], b1 = biasp[cl + 1];
            float* a = acc[mi][ni];
#pragma unroll
            for (int half = 0; half < 2; half++) {
                int row = row0 + half * 8;
                float v0 = a[half * 2 + 0] + b0;
                float v1 = a[half * 2 + 1] + b1;
                if (mode == 0) {
                    *(float2*)&g_if[(size_t)row * 2048 + bn + cl] =
                        make_float2(sigmoidf_(v0), sigmoidf_(v1));
                } else if (mode == 1) {
                    *(float2*)&g_cand[(size_t)row * 1024 + bn + cl] =
                        make_float2(tanhf(v0), tanhf(v1));
                } else {
                    float2 cn = *(const float2*)&g_cnew[(size_t)row * 1024 + bn + cl];
                    float hn0 = sigmoidf_(v0) * tanhf(cn.x);
                    float hn1 = sigmoidf_(v1) * tanhf(cn.y);
                    *(float2*)&g_hnew[(size_t)row * 1024 + bn + cl] = make_float2(hn0, hn1);
                    *(float2*)&outp[(size_t)row * 2050 + bn + cl] = make_float2(hn0, hn1);
                }
            }
        }
    }
#undef COPY_TILE
}

// ---------------- c_new = f*c + i*cand (+ fp16 split for o-gate) ----------------
__global__ __launch_bounds__(256) void cnew_kernel(
    const float* __restrict__ c, float* __restrict__ outp)
{
    size_t idx = ((size_t)blockIdx.x * 256 + threadIdx.x) * 4;
    size_t row = idx >> 10;
    int col = (int)(idx & 1023);
    float4 gi = *(const float4*)&g_if[row * 2048 + col];
    float4 gf = *(const float4*)&g_if[row * 2048 + 1024 + col];
    float4 gp = *(const float4*)&g_cand[idx];
    float4 cv = *(const float4*)&c[idx];
    float4 cn;
    cn.x = gf.x * cv.x + gi.x * gp.x;
    cn.y = gf.y * cv.y + gi.y * gp.y;
    cn.z = gf.z * cv.z + gi.z * gp.z;
    cn.w = gf.w * cv.w + gi.w * gp.w;
    *(float4*)&g_cnew[idx] = cn;
    float* doo = &outp[row * 2050 + 1024 + col];
    *(float2*)&doo[0] = make_float2(cn.x, cn.y);
    *(float2*)&doo[2] = make_float2(cn.z, cn.w);
    fp16 h0, l0, h1, l1, h2, l2, h3, l3;
    split_fp16(cn.x, h0, l0); split_fp16(cn.y, h1, l1);
    split_fp16(cn.z, h2, l2); split_fp16(cn.w, h3, l3);
    *(uint2*)(g_c2_hi + idx) = make_uint2(pack2h(h0, h1), pack2h(h2, h3));
    *(uint2*)(g_c2_lo + idx) = make_uint2(pack2h(l0, l1), pack2h(l2, l3));
}

// ---------------- micro = h_new @ W_m + b_m ----------------
__global__ __launch_bounds__(256) void micro_gemm(
    const float* __restrict__ Wm, const float* __restrict__ bmv)
{
    __shared__ float sH[64][33];
    __shared__ float sW[32][64];
    const int bm0 = blockIdx.x * 64;
    const int tid = threadIdx.x;
    const int tx = tid & 15, ty = tid >> 4;

    float acc[4][4];
#pragma unroll
    for (int i = 0; i < 4; i++)
#pragma unroll
        for (int j = 0; j < 4; j++) acc[i][j] = 0.0f;

    for (int k0 = 0; k0 < 1024; k0 += 32) {
#pragma unroll
        for (int i = 0; i < 2; i++) {
            int idx = tid + i * 256;
            int r = idx >> 3, c4 = (idx & 7) * 4;
            float4 v = *(const float4*)&g_hnew[(size_t)(bm0 + r) * 1024 + k0 + c4];
            sH[r][c4 + 0] = v.x; sH[r][c4 + 1] = v.y;
            sH[r][c4 + 2] = v.z; sH[r][c4 + 3] = v.w;
        }
#pragma unroll
        for (int i = 0; i < 2; i++) {
            int idx = tid + i * 256;
            int r = idx >> 4, c4 = (idx & 15) * 4;
            *(float4*)&sW[r][c4] = *(const float4*)&Wm[(size_t)(k0 + r) * 64 + c4];
        }
        __syncthreads();
#pragma unroll
        for (int kk = 0; kk < 32; kk++) {
            float a[4];
#pragma unroll
            for (int i = 0; i < 4; i++) a[i] = sH[ty * 4 + i][kk];
            float4 b4 = *(const float4*)&sW[kk][tx * 4];
            float b[4] = {b4.x, b4.y, b4.z, b4.w};
#pragma unroll
            for (int i = 0; i < 4; i++)
#pragma unroll
                for (int j = 0; j < 4; j++)
                    acc[i][j] = fmaf(a[i], b[j], acc[i][j]);
        }
        __syncthreads();
    }
    float4 bb = *(const float4*)&bmv[tx * 4];
    float bv[4] = {bb.x, bb.y, bb.z, bb.w};
#pragma unroll
    for (int i = 0; i < 4; i++) {
        int row = bm0 + ty * 4 + i;
        *(float4*)&g_micro[(size_t)row * 64 + tx * 4] =
            make_float4(acc[i][0] + bv[0], acc[i][1] + bv[1],
                        acc[i][2] + bv[2], acc[i][3] + bv[3]);
    }
}

// ---------------- finalize ----------------
__device__ __forceinline__ float warpred(float v) {
#pragma unroll
    for (int o = 16; o > 0; o >>= 1) v += __shfl_down_sync(0xffffffffu, v, o);
    return v;
}

__global__ __launch_bounds__(256) void finalize_kernel(
    const float* __restrict__ x,
    const float* __restrict__ mem,
    const float* __restrict__ u_gs,
    const float* __restrict__ u_a, const float* __restrict__ u_b,
    const float* __restrict__ w_a_h, const float* __restrict__ w_a_x,
    const float* __restrict__ w_a_r,
    const float* __restrict__ w_b_h, const float* __restrict__ w_b_x,
    const float* __restrict__ w_b_r,
    float* __restrict__ outp)
{
    __shared__ float s_micro[64];
    __shared__ float s_part[256];
    __shared__ float s_attn[16];
    __shared__ float s_red[20];

    const int b = blockIdx.x;
    const int t = threadIdx.x;
    const int lane = t & 31, wid = t >> 5;

    const float* hrow = g_hnew + (size_t)b * 1024;
    const float* xrow = x + (size_t)b * 1024;
    const float* mrow = mem + (size_t)b * 1024;

    {
        float4 h4 = *(const float4*)&hrow[t * 4];
        float4 x4 = *(const float4*)&xrow[t * 4];
        float4 ah = *(const float4*)&w_a_h[t * 4];
        float4 ax = *(const float4*)&w_a_x[t * 4];
        float4 bh = *(const float4*)&w_b_h[t * 4];
        float4 bx = *(const float4*)&w_b_x[t * 4];
        float pa = h4.x*ah.x + h4.y*ah.y + h4.z*ah.z + h4.w*ah.w
                 + x4.x*ax.x + x4.y*ax.y + x4.z*ax.z + x4.w*ax.w;
        float pb = h4.x*bh.x + h4.y*bh.y + h4.z*bh.z + h4.w*bh.w
                 + x4.x*bx.x + x4.y*bx.y + x4.z*bx.z + x4.w*bx.w;
        pa = warpred(pa); pb = warpred(pb);
        if (lane == 0) { s_red[wid] = pa; s_red[8 + wid] = pb; }
    }
    if (t < 16)
        *(float4*)&s_micro[t * 4] = *(const float4*)&g_micro[(size_t)b * 64 + t * 4];
    __syncthreads();

    {
        int m = t >> 4, q = t & 15;
        float4 m4 = *(const float4*)&mrow[m * 64 + q * 4];
        float4 u4 = *(const float4*)&s_micro[q * 4];
        s_part[t] = m4.x*u4.x + m4.y*u4.y + m4.z*u4.z + m4.w*u4.w;
    }
    __syncthreads();

    if (t < 16) {
        float lg = 0.0f;
#pragma unroll
        for (int q = 0; q < 16; q++) lg += s_part[t * 16 + q];
        float u = u_gs[(size_t)b * 16 + t];
        lg += -logf(-logf(u));
        lg /= TAUF;
        float mx = lg;
#pragma unroll
        for (int o = 8; o > 0; o >>= 1)
            mx = fmaxf(mx, __shfl_xor_sync(0xffffu, mx, o));
        float e = expf(lg - mx);
        float s = e;
#pragma unroll
        for (int o = 8; o > 0; o >>= 1)
            s += __shfl_xor_sync(0xffffu, s, o);
        s_attn[t] = e / s;
    }
    __syncthreads();

    if (t < 64) {
        float sv = 0.0f;
#pragma unroll
        for (int m = 0; m < 16; m++) sv += mrow[m * 64 + t] * s_attn[m];
        sv += 1.0f;
        float ra = sv * w_a_r[t];
        float rb = sv * w_b_r[t];
        ra = warpred(ra); rb = warpred(rb);
        if (lane == 0) { s_red[16 + wid] = ra; s_red[18 + wid] = rb; }
    }
    __syncthreads();

    if (t == 0) {
        float sa = 0.0f, sb = 0.0f;
#pragma unroll
        for (int w = 0; w < 8; w++) { sa += s_red[w]; sb += s_red[8 + w]; }
        sa += s_red[16] + s_red[17];
        sb += s_red[18] + s_red[19];
        float ua = u_a[b], ub = u_b[b];
        float la  = logf(ua) - log1pf(-ua);
        float lbv = logf(ub) - log1pf(-ub);
        outp[(size_t)b * 2050 + 2048] = sigmoidf_((sa + la)  / TAUF);
        outp[(size_t)b * 2050 + 2049] = sigmoidf_((sb + lbv) / TAUF);
    }
}

// ---------------------------------------------------------------------------
extern "C" void kernel_launch(void* const* d_in, const int* in_sizes, int n_in,
                              void* d_out, int out_size)
{
    const float* x      = (const float*)d_in[0];
    const float* h      = (const float*)d_in[1];
    const float* c      = (const float*)d_in[2];
    const float* memory = (const float*)d_in[3];
    const float* u_gs   = (const float*)d_in[4];
    const float* u_a    = (const float*)d_in[5];
    const float* u_b    = (const float*)d_in[6];
    const float* W_i    = (const float*)d_in[7];
    const float* b_i    = (const float*)d_in[8];
    const float* W_f    = (const float*)d_in[9];
    const float* b_f    = (const float*)d_in[10];
    const float* W_o    = (const float*)d_in[11];
    const float* b_o    = (const float*)d_in[12];
    const float* W_cand = (const float*)d_in[13];
    const float* b_cand = (const float*)d_in[14];
    const float* W_m    = (const float*)d_in[15];
    const float* b_m    = (const float*)d_in[16];
    const float* w_a_h  = (const float*)d_in[17];
    const float* w_a_x  = (const float*)d_in[18];
    const float* w_a_r  = (const float*)d_in[19];
    const float* w_b_h  = (const float*)d_in[20];
    const float* w_b_x  = (const float*)d_in[21];
    const float* w_b_r  = (const float*)d_in[22];
    float* out = (float*)d_out;

    // Idempotent, not a stream op — safe to call every time (no static guards).
    cudaFuncSetAttribute(gemm_hmma, cudaFuncAttributeMaxDynamicSharedMemorySize, SMEM_SZ);

    // conversions
    convA<<<(BB * 3072 / 4) / 256, 256>>>(x, h, c);
    convW<<<(3072 * 1024 / 4) / 256, 256>>>(W_i,    0);
    convW<<<(3072 * 1024 / 4) / 256, 256>>>(W_f,    1);
    convW<<<(3072 * 1024 / 4) / 256, 256>>>(W_o,    2);
    convW<<<(2048 * 1024 / 4) / 256, 256>>>(W_cand, 3);

    // gate GEMMs (CTA tile 128x256)
    gemm_hmma<<<dim3(8, 64), 256, SMEM_SZ>>>(3072, 0, b_i, b_f, out);        // i|f
    gemm_hmma<<<dim3(4, 64), 256, SMEM_SZ>>>(2048, 1, b_cand, nullptr, out); // cand

    cnew_kernel<<<(BHsz / 4) / 256, 256>>>(c, out);

    gemm_hmma<<<dim3(4, 64), 256, SMEM_SZ>>>(3072, 2, b_o, nullptr, out);    // o + h_new

    micro_gemm<<<BB / 64, 256>>>(W_m, b_m);
    finalize_kernel<<<BB, 256>>>(x, memory, u_gs, u_a, u_b,
                                 w_a_h, w_a_x, w_a_r,
                                 w_b_h, w_b_x, w_b_r, out);
}